// round 17
// baseline (speedup 1.0000x reference)
#include <cuda_runtime.h>
#include <cstdint>

// Problem constants
#define TABN    512             // table intervals over [-16, 16], h = 2^-4
#define NSTEP   32
#define NPATH   65536
#define DTC     0.03125f
#define SIG_CF  0.2f
#define CDT     0.0015625f      // DT * MU_C
#define CDT2    (CDT * CDT)

#define TPB     128
#define NBLK    (NPATH / TPB)   // 512
#define BK_TPB  576             // 9 points x 64 neurons
#define NBUILD  (TABN / 8)      // 64 builder blocks x 8 intervals
#define SEG     8               // steps per straight-line segment
#define NSEG    (NSTEP / SEG)   // 4

// Scratch (static device globals; no runtime allocation)
__device__ float4   g_tab[TABN];       // (y_i, dy_i, tanh_i, dtanh_i)
__device__ float2   g_part[NBLK];      // per-block (sum ycv^2, sum yT^2)
__device__ unsigned g_ready = 0;       // build-release flag (winner resets)
__device__ unsigned g_ctr   = 0;       // last-block ticket   (winner resets)

__device__ __forceinline__ void cp_async16(void* dst_smem, const void* src_gmem) {
    const uint32_t d = (uint32_t)__cvta_generic_to_shared(dst_smem);
    asm volatile("cp.async.cg.shared.global [%0], [%1], 16;\n" :: "r"(d), "l"(src_gmem));
}

// ---------------------------------------------------------------------------
// Build kernel (64 blocks): 9 overlapping MLP points -> 8 complete
// (value, slope) table entries per block. Releases path kernel via g_ready.
// Runs concurrently with the path kernel's dW staging (parallel graph nodes).
// ---------------------------------------------------------------------------
__global__ __launch_bounds__(BK_TPB) void build_kernel(
    const float* __restrict__ W1, const float* __restrict__ b1,
    const float* __restrict__ W2, const float* __restrict__ b2,
    const float* __restrict__ W3, const float* __restrict__ b3)
{
    __shared__ float sW2[64 * 64];   // 16 KB
    __shared__ float sh1[9 * 64];
    __shared__ float sred[18];
    __shared__ float sY[9];

    const int tid = threadIdx.x;

    {
        const float4* src = (const float4*)W2;
        float4* dst = (float4*)sW2;
        for (int i = tid; i < 1024; i += BK_TPB) dst[i] = src[i];
    }

    const int p  = tid >> 6;                 // local point 0..8
    const int j  = tid & 63;                 // output neuron 0..63
    const int pt = blockIdx.x * 8 + p;       // global table point
    const float h = 32.0f / (float)TABN;
    const float x = -16.0f + (float)pt * h;

    sh1[tid] = tanhf(fmaf(x, W1[64 + j], b1[j]));
    __syncthreads();

    float a = b2[j];
    #pragma unroll
    for (int k = 0; k < 64; k++)
        a = fmaf(sh1[p * 64 + k], sW2[k * 64 + j], a);

    float contrib = tanhf(a) * W3[2 * j];

    #pragma unroll
    for (int off = 16; off > 0; off >>= 1)
        contrib += __shfl_xor_sync(0xFFFFFFFFu, contrib, off);
    if ((tid & 31) == 0) sred[tid >> 5] = contrib;
    __syncthreads();

    if (tid < 9) sY[tid] = sred[2 * tid] + sred[2 * tid + 1] + b3[0];
    __syncthreads();

    if (tid < 8) {
        const int i = blockIdx.x * 8 + tid;
        const float xi = -16.0f + (float)i * h;
        const float t0 = tanhf(xi), t1 = tanhf(xi + h);
        g_tab[i] = make_float4(sY[tid], sY[tid + 1] - sY[tid], t0, t1 - t0);
    }
    __syncthreads();
    if (tid == 0) { __threadfence(); atomicAdd(&g_ready, 1u); }   // release
}

// ---------------------------------------------------------------------------
// Path kernel: the 32-step serial recurrence is replaced, per 8-step segment,
// by log-depth trees:
//   a_k = (1+CDT) + SIG*dW_k                       (all known upfront)
//   x-hat_k = x_seg * prefix-prod(a)               (Kogge-Stone, depth 3)
//   taming as 1st-order mult. correction: x_k = x-hat_k*(1 - CDT2*S_k),
//     S_k = prefix-sum(|x-hat_j|*(2-a_j))          (1/a ~= 2-a, err ~2e-6/seg)
//   -> ALL 8 table lookups independent (LDS latency fully pipelined)
//   ylin_n from exclusive prefix-sum of looked-up tanh (third tree)
// This converts a latency-bound 32-deep chain into issue/LDS-bound
// straight-line code. Fused deterministic reduction as before.
// ---------------------------------------------------------------------------
__global__ __launch_bounds__(TPB, 4) void path_kernel(
    const float* __restrict__ x0, const float* __restrict__ dW,
    float* __restrict__ out)
{
    __shared__ float4 stab[TABN];        // 8 KB table
    __shared__ float  sdw[TPB * 36];     // 18 KB dW tile, row stride 36
    const int tid = threadIdx.x;
    const int bb  = blockIdx.x;

    // 1) Fire all dW staging copies (cp.async: full MLP, L1 bypass)
    {
        const float4* g = (const float4*)dW + (size_t)bb * (TPB * 8);
        #pragma unroll
        for (int k = 0; k < 8; k++) {
            const int c = tid + TPB * k;                       // coalesced
            cp_async16(&((float4*)(sdw + (c >> 3) * 36))[c & 7], g + c);
        }
        asm volatile("cp.async.commit_group;\n" ::: "memory");
    }
    float x = __ldg(&x0[bb * TPB + tid]);

    // 2) Wait for the table (build runs concurrently on other SMs)
    if (tid == 0) {
        while (*((volatile unsigned*)&g_ready) < NBUILD) __nanosleep(32);
        __threadfence();                                       // acquire
    }
    __syncthreads();

    // 3) Stage table via L2 (.cg: produced by other SMs)
    #pragma unroll
    for (int k = 0; k < TABN / TPB; k++) {
        const int c = tid + TPB * k;
        stab[c] = __ldcg(&g_tab[c]);
    }
    asm volatile("cp.async.wait_group 0;\n" ::: "memory");
    __syncthreads();

    const float4* __restrict__ row = (const float4*)(sdw + tid * 36);

    float ylin = 1.0f, acc = 0.0f;

    #pragma unroll
    for (int seg = 0; seg < NSEG; seg++) {
        // Load this segment's 8 dW values (2 conflict-free LDS.128)
        float dwh[SEG];
        {
            const float4 v0 = row[2 * seg], v1 = row[2 * seg + 1];
            dwh[0] = v0.x; dwh[1] = v0.y; dwh[2] = v0.z; dwh[3] = v0.w;
            dwh[4] = v1.x; dwh[5] = v1.y; dwh[6] = v1.z; dwh[7] = v1.w;
        }

        // Per-step factors and reciprocal proxies (independent FMAs)
        float a[SEG], r[SEG];
        #pragma unroll
        for (int k = 0; k < SEG; k++) {
            a[k] = fmaf(SIG_CF, dwh[k], 1.0f + CDT);
            r[k] = fmaf(-SIG_CF, dwh[k], 1.0f - CDT);   // = 2 - a[k]
        }

        // Inclusive prefix product of a (Kogge-Stone, depth 3, in place)
        #pragma unroll
        for (int k = SEG - 1; k >= 1; k--) a[k] *= a[k - 1];
        #pragma unroll
        for (int k = SEG - 1; k >= 2; k--) a[k] *= a[k - 2];
        #pragma unroll
        for (int k = SEG - 1; k >= 4; k--) a[k] *= a[k - 4];

        // Uncorrected states: xs[k] = x * prod_{j<k} a_j  (exclusive)
        float xs[SEG];
        xs[0] = x;
        #pragma unroll
        for (int k = 1; k < SEG; k++) xs[k] = x * a[k - 1];
        const float xe_hat = x * a[SEG - 1];

        // Taming correction terms t[k] = |xs_k| * (2 - a_k); prefix-sum them
        float t[SEG];
        #pragma unroll
        for (int k = 0; k < SEG; k++) t[k] = fabsf(xs[k]) * r[k];
        #pragma unroll
        for (int k = SEG - 1; k >= 1; k--) t[k] += t[k - 1];
        #pragma unroll
        for (int k = SEG - 1; k >= 2; k--) t[k] += t[k - 2];
        #pragma unroll
        for (int k = SEG - 1; k >= 4; k--) t[k] += t[k - 4];

        // Corrected states (exclusive prefix of t)
        #pragma unroll
        for (int k = 1; k < SEG; k++)
            xs[k] *= fmaf(-CDT2, t[k - 1], 1.0f);
        const float xe = xe_hat * fmaf(-CDT2, t[SEG - 1], 1.0f);

        // 8 INDEPENDENT table lookups (magic-number indexing, LDS pipelined)
        float yv[SEG], th[SEG];
        #pragma unroll
        for (int k = 0; k < SEG; k++) {
            const float u  = fmaf(xs[k], 16.0f, 256.0f);   // (x+16)*16
            const float uf = u + 8388607.5f;               // 2^23 - 0.5
            const int   i  = __float_as_int(uf) & (TABN - 1);
            const float f  = u - (uf - 8388608.0f);
            const float4 e = stab[i];
            yv[k] = fmaf(f, e.y, e.x);
            th[k] = fmaf(f, e.w, e.z);
        }

        // Prefix-sum of tanh for ylin; accumulate ycv^2
        #pragma unroll
        for (int k = SEG - 1; k >= 1; k--) th[k] += th[k - 1];
        #pragma unroll
        for (int k = SEG - 1; k >= 2; k--) th[k] += th[k - 2];
        #pragma unroll
        for (int k = SEG - 1; k >= 4; k--) th[k] += th[k - 4];

        {
            const float yc = yv[0] - ylin;
            acc = fmaf(yc, yc, acc);
        }
        #pragma unroll
        for (int k = 1; k < SEG; k++) {
            const float yc = fmaf(DTC, th[k - 1], yv[k] - ylin);
            acc = fmaf(yc, yc, acc);
        }

        ylin = fmaf(-DTC, th[SEG - 1], ylin);
        x = xe;
    }

    float yT2 = ylin * ylin;

    // Deterministic block reduction (4 warps)
    #pragma unroll
    for (int off = 16; off > 0; off >>= 1) {
        acc += __shfl_xor_sync(0xFFFFFFFFu, acc, off);
        yT2 += __shfl_xor_sync(0xFFFFFFFFu, yT2, off);
    }
    __shared__ float2 sp[TPB / 32];
    __shared__ bool   s_last;
    if ((tid & 31) == 0) sp[tid >> 5] = make_float2(acc, yT2);
    __syncthreads();
    if (tid == 0) {
        float s1 = 0.0f, s2 = 0.0f;
        #pragma unroll
        for (int w = 0; w < TPB / 32; w++) { s1 += sp[w].x; s2 += sp[w].y; }
        g_part[bb] = make_float2(s1, s2);
        __threadfence();
        const unsigned t = atomicAdd(&g_ctr, 1u);
        s_last = (t == NBLK - 1);
    }
    __syncthreads();

    // Winner block: deterministic fixed-order final reduction + flag reset
    if (s_last) {
        __threadfence();
        double a1 = 0.0, a2 = 0.0;
        #pragma unroll
        for (int k = tid; k < NBLK; k += TPB) {
            const float2 pp = g_part[k];
            a1 += (double)pp.x;
            a2 += (double)pp.y;
        }
        #pragma unroll
        for (int off = 16; off > 0; off >>= 1) {
            a1 += __shfl_xor_sync(0xFFFFFFFFu, a1, off);
            a2 += __shfl_xor_sync(0xFFFFFFFFu, a2, off);
        }
        __shared__ double sd[8];
        if ((tid & 31) == 0) {
            sd[tid >> 5]       = a1;
            sd[4 + (tid >> 5)] = a2;
        }
        __syncthreads();
        if (tid == 0) {
            const double s1 = sd[0] + sd[1] + sd[2] + sd[3];
            const double s2 = sd[4] + sd[5] + sd[6] + sd[7];
            const double loss = s1 / (double)((long long)NSTEP * NPATH)
                              + 0.01 * (s2 / (double)NPATH);
            out[0]  = (float)loss;
            g_ready = 0;                         // reset for next replay
            g_ctr   = 0;
        }
    }
}

// ---------------------------------------------------------------------------
// Launch: build and path as PARALLEL graph nodes (event fork/join); the
// device-side flag carries the real dependency.
// Inputs (metadata order): x0, dW, W1, b1, W2, b2, W3, b3
// ---------------------------------------------------------------------------
extern "C" void kernel_launch(void* const* d_in, const int* in_sizes, int n_in,
                              void* d_out, int out_size)
{
    const float* x0 = (const float*)d_in[0];
    const float* dW = (const float*)d_in[1];
    const float* W1 = (const float*)d_in[2];
    const float* b1 = (const float*)d_in[3];
    const float* W2 = (const float*)d_in[4];
    const float* b2 = (const float*)d_in[5];
    const float* W3 = (const float*)d_in[6];
    const float* b3 = (const float*)d_in[7];
    (void)in_sizes; (void)n_in; (void)out_size;

    cudaStream_t s2;
    cudaEvent_t evA, evB;
    cudaStreamCreateWithFlags(&s2, cudaStreamNonBlocking);
    cudaEventCreateWithFlags(&evA, cudaEventDisableTiming);
    cudaEventCreateWithFlags(&evB, cudaEventDisableTiming);

    // Fork: path kernel on s2 runs concurrently with build on the main stream
    cudaEventRecord(evA, 0);
    cudaStreamWaitEvent(s2, evA, 0);

    build_kernel<<<NBUILD, BK_TPB>>>(W1, b1, W2, b2, W3, b3);
    path_kernel<<<NBLK, TPB, 0, s2>>>(x0, dW, (float*)d_out);

    // Join back onto the main stream
    cudaEventRecord(evB, s2);
    cudaStreamWaitEvent(0, evB, 0);
}